// round 10
// baseline (speedup 1.0000x reference)
#include <cuda_runtime.h>
#include <cuda_fp16.h>
#include <cuda_bf16.h>
#include <math.h>
#include <stdint.h>

// Problem constants
#define B_ROWS   16384
#define DIM      2048
#define OUT_CL   1000
#define N_INNER  255
#define N_LEAF   256

#define BK      32
#define NCHUNK  (DIM / BK)
#define SCALE     1024.0f
#define SCALE_INV (1.0f / (1024.0f * 1024.0f))

// ---------------- device scratch ----------------
__device__ float  g_probs[(size_t)B_ROWS * 256];
__device__ float  g_Q[(size_t)N_LEAF * OUT_CL];
__device__ float  g_logQt[(size_t)OUT_CL * N_LEAF];
__device__ float  g_leafSum[N_LEAF];
__device__ double g_lossSum;
__device__ int    g_t[B_ROWS];
// W split to fp16 hi/lo, scaled by 1024: [n][chunk][hi 0..31 | lo 32..63]
__device__ __half g_Wsp[(size_t)256 * DIM * 2];

// ---------------- helpers ----------------
__device__ __forceinline__ uint32_t smem_u32(const void* p) {
    uint32_t a;
    asm("{ .reg .u64 t; cvta.to.shared.u64 t, %1; cvt.u32.u64 %0, t; }" : "=r"(a) : "l"(p));
    return a;
}
__device__ __forceinline__ void mma16(float* c, const uint32_t* a, const uint32_t* b) {
    asm volatile("mma.sync.aligned.m16n8k16.row.col.f32.f16.f16.f32 "
        "{%0,%1,%2,%3}, {%4,%5,%6,%7}, {%8,%9}, {%0,%1,%2,%3};"
        : "+f"(c[0]), "+f"(c[1]), "+f"(c[2]), "+f"(c[3])
        : "r"(a[0]), "r"(a[1]), "r"(a[2]), "r"(a[3]), "r"(b[0]), "r"(b[1]));
}
#define LDSM4(r, a) asm volatile("ldmatrix.sync.aligned.m8n8.x4.shared.b16 {%0,%1,%2,%3}, [%4];" \
    : "=r"((r)[0]), "=r"((r)[1]), "=r"((r)[2]), "=r"((r)[3]) : "r"(a))
#define CP_ASYNC16(dst, src) asm volatile("cp.async.cg.shared.global [%0], [%1], 16;" :: "r"(dst), "l"(src))
#define CP_COMMIT()          asm volatile("cp.async.commit_group;")
#define CP_WAIT0()           asm volatile("cp.async.wait_group 0;" ::: "memory")

// ---------------- init ----------------
__global__ void init_kernel() {
    int t = threadIdx.x;
    if (t < N_LEAF) g_leafSum[t] = 0.0f;
    if (t == 0) g_lossSum = 0.0;
}

// ---------------- W split to fp16 hi/lo (scaled by 1024) ----------------
__global__ void wsplit_kernel(const float* __restrict__ W) {
    int n = blockIdx.x;
    for (int k = threadIdx.x; k < DIM; k += 256) {
        float w = (n < N_INNER) ? W[(size_t)n * DIM + k] * SCALE : 0.0f;
        __half h = __float2half_rn(w);
        __half l = __float2half_rn(w - __half2float(h));
        int ch = k >> 5, s = k & 31;
        size_t base = (size_t)n * (DIM * 2) + ch * 64;
        g_Wsp[base + s]      = h;
        g_Wsp[base + 32 + s] = l;
    }
}

// ---------------- log_softmax of leaf_params ----------------
__global__ void softmax_kernel(const float* __restrict__ lp) {
    __shared__ float red[256];
    int r = blockIdx.x;
    int tid = threadIdx.x;
    const float* row = lp + (size_t)r * OUT_CL;

    float m = -INFINITY;
    for (int j = tid; j < OUT_CL; j += 256) m = fmaxf(m, row[j]);
    red[tid] = m; __syncthreads();
    for (int s = 128; s; s >>= 1) { if (tid < s) red[tid] = fmaxf(red[tid], red[tid + s]); __syncthreads(); }
    float rowmax = red[0];
    __syncthreads();

    float sum = 0.0f;
    for (int j = tid; j < OUT_CL; j += 256) sum += expf(row[j] - rowmax);
    red[tid] = sum; __syncthreads();
    for (int s = 128; s; s >>= 1) { if (tid < s) red[tid] += red[tid + s]; __syncthreads(); }
    float lse = rowmax + logf(red[0]);

    for (int j = tid; j < OUT_CL; j += 256) {
        float lq = row[j] - lse;
        g_Q[(size_t)r * OUT_CL + j] = expf(lq);
        g_logQt[(size_t)j * N_LEAF + r] = lq;
    }
}

// ---------------- target extraction (one-hot, early exit) ----------------
__global__ void target_kernel(const float* __restrict__ y) {
    int warp = threadIdx.x >> 5, lane = threadIdx.x & 31;
    int gw = blockIdx.x * (blockDim.x >> 5) + warp;
    int nw = gridDim.x * (blockDim.x >> 5);
    for (int b = gw; b < B_ROWS; b += nw) {
        const float* row = y + (size_t)b * OUT_CL;
        int found = 0;
        for (int jb = 0; jb < 1024; jb += 32) {
            int j = jb + lane;
            float v = (j < OUT_CL) ? __ldg(row + j) : 0.0f;
            unsigned msk = __ballot_sync(0xffffffffu, v > 0.5f);
            if (msk) {
                int src = __ffs(msk) - 1;
                found = jb + src;
                break;
            }
        }
        if (lane == 0) g_t[b] = found;
    }
}

// ---------------- fp16 3-product mma GEMM ----------------
// CTA: 256 threads = 8 warps (2 M x 4 N), tile M=64 N=128, 2 CTAs/SM.
// SMEM: A bufs 2x8KB @0, B bufs 2x16KB @16384. Total 48KB.
#define GEMM_SMEM 49152

__global__ __launch_bounds__(256, 2)
void gemm_mma_kernel(const float* __restrict__ X,
                     const float* __restrict__ bias, const float* __restrict__ beta) {
    extern __shared__ __align__(16) char smemc[];
    const int tid  = threadIdx.x;
    const int lane = tid & 31, wid = tid >> 5;
    const int warpM = wid & 1, warpN = wid >> 1;
    const int mBase = blockIdx.y * 64;
    const int nBase = blockIdx.x * 128;
    const uint32_t sb = smem_u32(smemc);

    const int aRow = warpM * 32 + (lane & 15);
    const int aU   = lane >> 4;
    const int bRow = warpN * 32 + (lane & 7) + ((lane >> 4) << 3);
    const int bU   = (lane >> 3) & 1;

    // A fill: 4 threads/row, 8 floats each. B fill: 2 threads/row, 4x16B each.
    const int afrow = tid >> 2, afoct = tid & 3;
    const int bfrow = tid >> 1, bfu0 = (tid & 1) * 4;

    float c[2][4][4];
    #pragma unroll
    for (int i = 0; i < 2; i++)
        #pragma unroll
        for (int j = 0; j < 4; j++)
            #pragma unroll
            for (int k = 0; k < 4; k++) c[i][j][k] = 0.0f;

    auto aAddr = [&](int buf, int mt, int u0) -> uint32_t {
        int row = aRow + mt * 16;
        return sb + buf * 8192 + row * 128 + (((u0 + aU) ^ (row & 7)) << 4);
    };
    auto bAddr = [&](int buf, int ntp, int u0) -> uint32_t {
        int row = bRow + ntp * 16;
        return sb + 16384 + buf * 16384 + row * 128 + (((u0 + bU) ^ (row & 7)) << 4);
    };

    auto issueB = [&](int ch, int buf) {
        const __half* src = g_Wsp + (size_t)(nBase + bfrow) * (DIM * 2) + ch * 64;
        uint32_t dstRow = sb + 16384 + buf * 16384 + bfrow * 128;
        int x = bfrow & 7;
        #pragma unroll
        for (int u = 0; u < 4; u++)
            CP_ASYNC16(dstRow + (((bfu0 + u) ^ x) << 4), src + (bfu0 + u) * 8);
    };
    auto loadA = [&](int ch, float4* v) {
        const float* src = X + (size_t)(mBase + afrow) * DIM + ch * BK + afoct * 8;
        v[0] = *(const float4*)(src);
        v[1] = *(const float4*)(src + 4);
    };
    auto storeA = [&](const float4* v, int buf) {
        __half h[8], l[8];
        const float* f = (const float*)v;
        #pragma unroll
        for (int i = 0; i < 8; i++) {
            float s = f[i] * SCALE;
            h[i] = __float2half_rn(s);
            l[i] = __float2half_rn(s - __half2float(h[i]));
        }
        uint32_t rowAddr = sb + buf * 8192 + afrow * 128;
        int x = afrow & 7;
        uint32_t aH = rowAddr + ((afoct ^ x) << 4);
        uint32_t aL = rowAddr + (((4 + afoct) ^ x) << 4);
        uint4 ph = *(const uint4*)h;
        uint4 pl = *(const uint4*)l;
        asm volatile("st.shared.v4.b32 [%0], {%1,%2,%3,%4};" :: "r"(aH), "r"(ph.x), "r"(ph.y), "r"(ph.z), "r"(ph.w));
        asm volatile("st.shared.v4.b32 [%0], {%1,%2,%3,%4};" :: "r"(aL), "r"(pl.x), "r"(pl.y), "r"(pl.z), "r"(pl.w));
    };

    {
        issueB(0, 0); CP_COMMIT();
        float4 v[2];
        loadA(0, v);
        storeA(v, 0);
        CP_WAIT0();
        __syncthreads();
    }

    for (int ch = 0; ch < NCHUNK; ch++) {
        const int cur = ch & 1, nxt = cur ^ 1;
        float4 v[2];
        if (ch + 1 < NCHUNK) {
            loadA(ch + 1, v);
            issueB(ch + 1, nxt); CP_COMMIT();
        }

        #pragma unroll
        for (int kst = 0; kst < 2; kst++) {
            const int uH = 2 * kst, uL = 4 + 2 * kst;
            uint32_t aH[2][4], aL[2][4], bH[2][4], bL[2][4];
            LDSM4(aH[0], aAddr(cur, 0, uH)); LDSM4(aH[1], aAddr(cur, 1, uH));
            LDSM4(aL[0], aAddr(cur, 0, uL)); LDSM4(aL[1], aAddr(cur, 1, uL));
            LDSM4(bH[0], bAddr(cur, 0, uH)); LDSM4(bH[1], bAddr(cur, 1, uH));
            LDSM4(bL[0], bAddr(cur, 0, uL)); LDSM4(bL[1], bAddr(cur, 1, uL));
            #pragma unroll
            for (int mt = 0; mt < 2; mt++)
                #pragma unroll
                for (int ntp = 0; ntp < 2; ntp++) {
                    mma16(c[mt][ntp * 2],     aH[mt], bH[ntp]);
                    mma16(c[mt][ntp * 2 + 1], aH[mt], bH[ntp] + 2);
                    mma16(c[mt][ntp * 2],     aH[mt], bL[ntp]);
                    mma16(c[mt][ntp * 2 + 1], aH[mt], bL[ntp] + 2);
                    mma16(c[mt][ntp * 2],     aL[mt], bH[ntp]);
                    mma16(c[mt][ntp * 2 + 1], aL[mt], bH[ntp] + 2);
                }
        }

        if (ch + 1 < NCHUNK) {
            storeA(v, nxt);
            CP_WAIT0();
        }
        __syncthreads();
    }

    const int group = lane >> 2, tig = lane & 3;
    #pragma unroll
    for (int mt = 0; mt < 2; mt++) {
        int r0 = mBase + warpM * 32 + mt * 16 + group;
        #pragma unroll
        for (int nt = 0; nt < 4; nt++) {
            int n0 = nBase + warpN * 32 + nt * 8 + tig * 2;
            float be0 = (n0     < N_INNER) ? __ldg(beta + n0)     : 0.0f;
            float be1 = (n0 + 1 < N_INNER) ? __ldg(beta + n0 + 1) : 0.0f;
            float bi0 = (n0     < N_INNER) ? __ldg(bias + n0)     : 0.0f;
            float bi1 = (n0 + 1 < N_INNER) ? __ldg(bias + n0 + 1) : 0.0f;
            float2 o0, o1;
            {
                float z = be0 * (c[mt][nt][0] * SCALE_INV + bi0);
                o0.x = (n0 < N_INNER) ? 1.0f / (1.0f + expf(-z)) : 0.0f;
            }
            {
                float z = be1 * (c[mt][nt][1] * SCALE_INV + bi1);
                o0.y = (n0 + 1 < N_INNER) ? 1.0f / (1.0f + expf(-z)) : 0.0f;
            }
            {
                float z = be0 * (c[mt][nt][2] * SCALE_INV + bi0);
                o1.x = (n0 < N_INNER) ? 1.0f / (1.0f + expf(-z)) : 0.0f;
            }
            {
                float z = be1 * (c[mt][nt][3] * SCALE_INV + bi1);
                o1.y = (n0 + 1 < N_INNER) ? 1.0f / (1.0f + expf(-z)) : 0.0f;
            }
            *(float2*)(g_probs + (size_t)r0 * 256 + n0)       = o0;
            *(float2*)(g_probs + (size_t)(r0 + 8) * 256 + n0) = o1;
        }
    }
}

// ---------------- tree expansion + fused output gather ----------------
__global__ __launch_bounds__(256)
void path_kernel(float* __restrict__ outRows) {
    __shared__ float sp[8][256];
    __shared__ float ls[256];
    __shared__ float red[256];
    const int warp = threadIdx.x >> 5, lane = threadIdx.x & 31;
    const int gw = blockIdx.x * 8 + warp;
    const int nw = gridDim.x * 8;
    const int base = lane * 8;

    ls[threadIdx.x] = 0.0f;
    __syncthreads();

    float lacc[8];
    #pragma unroll
    for (int k = 0; k < 8; k++) lacc[k] = 0.0f;
    float dacc = 0.0f;

    for (int b = gw; b < B_ROWS; b += nw) {
        const float* pr = g_probs + (size_t)b * 256;
        for (int i = lane; i < 256; i += 32) sp[warp][i] = pr[i];
        __syncwarp();

        float pre = 1.0f;
        #pragma unroll
        for (int d = 1; d <= 5; d++) {
            int g = (1 << (d - 1)) - 1 + (base >> (9 - d));
            int bit = (base >> (8 - d)) & 1;
            float pv = sp[warp][g];
            pre *= bit ? pv : (1.0f - pv);
        }
        float leaf[8];
        #pragma unroll
        for (int k = 0; k < 8; k++) {
            int l = base + k;
            float f = pre;
            #pragma unroll
            for (int d = 6; d <= 8; d++) {
                int g = (1 << (d - 1)) - 1 + (l >> (9 - d));
                int bit = (l >> (8 - d)) & 1;
                float pv = sp[warp][g];
                f *= bit ? pv : (1.0f - pv);
            }
            leaf[k] = f;
            lacc[k] += f;
        }

        int t = g_t[b];
        const float* lq = g_logQt + (size_t)t * 256 + base;
        float dl = 0.0f;
        #pragma unroll
        for (int k = 0; k < 8; k++) dl += leaf[k] * lq[k];
        dacc += dl;

        float bv = leaf[0]; int bi = base;
        #pragma unroll
        for (int k = 1; k < 8; k++) if (leaf[k] > bv) { bv = leaf[k]; bi = base + k; }
        for (int off = 16; off; off >>= 1) {
            float ov = __shfl_down_sync(0xffffffffu, bv, off);
            int   oi = __shfl_down_sync(0xffffffffu, bi, off);
            if (ov > bv || (ov == bv && oi < bi)) { bv = ov; bi = oi; }
        }
        bi = __shfl_sync(0xffffffffu, bi, 0);

        const float* q = g_Q + (size_t)bi * OUT_CL;
        float* o = outRows + (size_t)b * OUT_CL;
        #pragma unroll 4
        for (int j = lane; j < OUT_CL; j += 32) o[j] = __ldg(q + j);
        __syncwarp();
    }

    #pragma unroll
    for (int k = 0; k < 8; k++) atomicAdd(&ls[base + k], lacc[k]);
    __syncthreads();
    atomicAdd(&g_leafSum[threadIdx.x], ls[threadIdx.x]);

    red[threadIdx.x] = dacc;
    __syncthreads();
    for (int s = 128; s; s >>= 1) { if (threadIdx.x < s) red[threadIdx.x] += red[threadIdx.x + s]; __syncthreads(); }
    if (threadIdx.x == 0) atomicAdd(&g_lossSum, (double)red[0]);
}

// ---------------- finalize (parallel heap + alpha) ----------------
__global__ void final_kernel(float* __restrict__ out, int writeLoss) {
    __shared__ float H[255];
    __shared__ float Cs[128];
    const int tid = threadIdx.x;

    if (tid < 128) H[127 + tid] = g_leafSum[2 * tid] + g_leafSum[2 * tid + 1];
    __syncthreads();
    for (int n = 64; n >= 1; n >>= 1) {
        int b0 = n - 1;
        if (tid < n) H[b0 + tid] = H[2 * (b0 + tid) + 1] + H[2 * (b0 + tid) + 2];
        __syncthreads();
    }

    float cpart = 0.0f;
    if (tid < 127) {
        int g = tid;
        int d = 32 - __clz(g + 1);
        float lm = 0.1f * exp2f((float)(-d)) * 0.5f;
        float denom = H[g];
        if (denom == 0.0f) denom = 1e-6f;
        float a = H[2 * g + 2] / denom;
        a = fminf(fmaxf(a, 1e-6f), 1.0f - 1e-6f);
        cpart = -lm * (logf(a) + log1pf(-a));
    }
    Cs[tid] = cpart;
    __syncthreads();
    for (int s = 64; s; s >>= 1) { if (tid < s) Cs[tid] += Cs[tid + s]; __syncthreads(); }
    if (tid == 0 && writeLoss) {
        double lt = g_lossSum / (double)B_ROWS;
        out[0] = (float)(-lt + (double)Cs[0]);
    }
}

extern "C" void kernel_launch(void* const* d_in, const int* in_sizes, int n_in,
                              void* d_out, int out_size) {
    const float* x    = (const float*)d_in[0];
    const float* y    = (const float*)d_in[1];
    const float* W    = (const float*)d_in[2];
    const float* bias = (const float*)d_in[3];
    const float* beta = (const float*)d_in[4];
    const float* lp   = (const float*)d_in[5];
    float* out = (float*)d_out;

    int hasLoss = (out_size >= B_ROWS * OUT_CL + 1) ? 1 : 0;
    float* outRows = out + hasLoss;

    static int smemSet = 0;
    if (!smemSet) {
        cudaFuncSetAttribute(gemm_mma_kernel, cudaFuncAttributeMaxDynamicSharedMemorySize, GEMM_SMEM);
        smemSet = 1;
    }

    init_kernel<<<1, 256>>>();
    wsplit_kernel<<<256, 256>>>(W);
    softmax_kernel<<<N_LEAF, 256>>>(lp);
    gemm_mma_kernel<<<dim3(2, 256), 256, GEMM_SMEM>>>(x, bias, beta);
    target_kernel<<<2048, 256>>>(y);
    path_kernel<<<512, 256>>>(outRows);
    final_kernel<<<1, 128>>>(out, hasLoss);
}

// round 15
// speedup vs baseline: 1.5775x; 1.5775x over previous
#include <cuda_runtime.h>
#include <cuda_fp16.h>
#include <cuda_bf16.h>
#include <math.h>
#include <stdint.h>

// Problem constants
#define B_ROWS   16384
#define DIM      2048
#define OUT_CL   1000
#define N_INNER  255
#define N_LEAF   256

#define BK      32
#define NCHUNK  (DIM / BK)
#define SCALE     1024.0f
#define SCALE_INV (1.0f / (1024.0f * 1024.0f))

// ---------------- device scratch ----------------
__device__ float  g_probs[(size_t)B_ROWS * 256];
__device__ float  g_Q[(size_t)N_LEAF * OUT_CL];
__device__ float  g_logQt[(size_t)OUT_CL * N_LEAF];
__device__ float  g_leafSum[N_LEAF];
__device__ double g_lossSum;
__device__ int    g_t[B_ROWS];
// W split to fp16 hi/lo, scaled by 1024: [n][chunk][hi 0..31 | lo 32..63]
__device__ __half g_Wsp[(size_t)256 * DIM * 2];

// ---------------- helpers ----------------
__device__ __forceinline__ uint32_t smem_u32(const void* p) {
    uint32_t a;
    asm("{ .reg .u64 t; cvta.to.shared.u64 t, %1; cvt.u32.u64 %0, t; }" : "=r"(a) : "l"(p));
    return a;
}
__device__ __forceinline__ void mma16(float* c, const uint32_t* a, const uint32_t* b) {
    asm volatile("mma.sync.aligned.m16n8k16.row.col.f32.f16.f16.f32 "
        "{%0,%1,%2,%3}, {%4,%5,%6,%7}, {%8,%9}, {%0,%1,%2,%3};"
        : "+f"(c[0]), "+f"(c[1]), "+f"(c[2]), "+f"(c[3])
        : "r"(a[0]), "r"(a[1]), "r"(a[2]), "r"(a[3]), "r"(b[0]), "r"(b[1]));
}
#define LDSM4(r, a) asm volatile("ldmatrix.sync.aligned.m8n8.x4.shared.b16 {%0,%1,%2,%3}, [%4];" \
    : "=r"((r)[0]), "=r"((r)[1]), "=r"((r)[2]), "=r"((r)[3]) : "r"(a))
#define CP_ASYNC16(dst, src) asm volatile("cp.async.cg.shared.global [%0], [%1], 16;" :: "r"(dst), "l"(src))
#define CP_COMMIT()          asm volatile("cp.async.commit_group;")
#define CP_WAIT1()           asm volatile("cp.async.wait_group 1;" ::: "memory")

// ---------------- init ----------------
__global__ void init_kernel() {
    int t = threadIdx.x;
    if (t < N_LEAF) g_leafSum[t] = 0.0f;
    if (t == 0) g_lossSum = 0.0;
}

// ---------------- W split to fp16 hi/lo (scaled by 1024) ----------------
__global__ void wsplit_kernel(const float* __restrict__ W) {
    int n = blockIdx.x;
    for (int k = threadIdx.x; k < DIM; k += 256) {
        float w = (n < N_INNER) ? W[(size_t)n * DIM + k] * SCALE : 0.0f;
        __half h = __float2half_rn(w);
        __half l = __float2half_rn(w - __half2float(h));
        int ch = k >> 5, s = k & 31;
        size_t base = (size_t)n * (DIM * 2) + ch * 64;
        g_Wsp[base + s]      = h;
        g_Wsp[base + 32 + s] = l;
    }
}

// ---------------- log_softmax of leaf_params ----------------
__global__ void softmax_kernel(const float* __restrict__ lp) {
    __shared__ float red[256];
    int r = blockIdx.x;
    int tid = threadIdx.x;
    const float* row = lp + (size_t)r * OUT_CL;

    float m = -INFINITY;
    for (int j = tid; j < OUT_CL; j += 256) m = fmaxf(m, row[j]);
    red[tid] = m; __syncthreads();
    for (int s = 128; s; s >>= 1) { if (tid < s) red[tid] = fmaxf(red[tid], red[tid + s]); __syncthreads(); }
    float rowmax = red[0];
    __syncthreads();

    float sum = 0.0f;
    for (int j = tid; j < OUT_CL; j += 256) sum += expf(row[j] - rowmax);
    red[tid] = sum; __syncthreads();
    for (int s = 128; s; s >>= 1) { if (tid < s) red[tid] += red[tid + s]; __syncthreads(); }
    float lse = rowmax + logf(red[0]);

    for (int j = tid; j < OUT_CL; j += 256) {
        float lq = row[j] - lse;
        g_Q[(size_t)r * OUT_CL + j] = expf(lq);
        g_logQt[(size_t)j * N_LEAF + r] = lq;
    }
}

// ---------------- target extraction (one-hot, early exit) ----------------
__global__ void target_kernel(const float* __restrict__ y) {
    int warp = threadIdx.x >> 5, lane = threadIdx.x & 31;
    int gw = blockIdx.x * (blockDim.x >> 5) + warp;
    int nw = gridDim.x * (blockDim.x >> 5);
    for (int b = gw; b < B_ROWS; b += nw) {
        const float* row = y + (size_t)b * OUT_CL;
        int found = 0;
        for (int jb = 0; jb < 1024; jb += 32) {
            int j = jb + lane;
            float v = (j < OUT_CL) ? __ldg(row + j) : 0.0f;
            unsigned msk = __ballot_sync(0xffffffffu, v > 0.5f);
            if (msk) {
                int src = __ffs(msk) - 1;
                found = jb + src;
                break;
            }
        }
        if (lane == 0) g_t[b] = found;
    }
}

// ---------------- fp16 3-product mma GEMM ----------------
// CTA: 512 threads = 16 warps (4 M x 4 N), tile 128x128, warp tile 32x32.
// A: 2 buffers x 16KB @0 (in-kernel split). B: 3 stages x 16KB @32768 (cp.async ring).
// One __syncthreads per chunk; wait_group 1 so next B fetch hides under compute.
#define GEMM_SMEM (2 * 16384 + 3 * 16384)

__global__ __launch_bounds__(512, 1)
void gemm_mma_kernel(const float* __restrict__ X,
                     const float* __restrict__ bias, const float* __restrict__ beta) {
    extern __shared__ __align__(16) char smemc[];
    const int tid  = threadIdx.x;
    const int lane = tid & 31, wid = tid >> 5;
    const int warpM = wid & 3, warpN = wid >> 2;
    const int mBase = blockIdx.y * 128;
    const int nBase = blockIdx.x * 128;
    const uint32_t sb = smem_u32(smemc);

    const int aRow = warpM * 32 + (lane & 15);
    const int aU   = lane >> 4;
    const int bRow = warpN * 32 + (lane & 7) + ((lane >> 4) << 3);
    const int bU   = (lane >> 3) & 1;

    const int frow = tid >> 2;           // 0..127 fill row
    const int foct = tid & 3;            // 4 threads per row

    float c[2][4][4];
    #pragma unroll
    for (int i = 0; i < 2; i++)
        #pragma unroll
        for (int j = 0; j < 4; j++)
            #pragma unroll
            for (int k = 0; k < 4; k++) c[i][j][k] = 0.0f;

    auto aAddr = [&](int buf, int mt, int u0) -> uint32_t {
        int row = aRow + mt * 16;
        return sb + buf * 16384 + row * 128 + (((u0 + aU) ^ (row & 7)) << 4);
    };
    auto bAddr = [&](int stg, int ntp, int u0) -> uint32_t {
        int row = bRow + ntp * 16;
        return sb + 32768 + stg * 16384 + row * 128 + (((u0 + bU) ^ (row & 7)) << 4);
    };

    auto issueB = [&](int ch, int stg) {
        const __half* src = g_Wsp + (size_t)(nBase + frow) * (DIM * 2) + ch * 64;
        uint32_t dstRow = sb + 32768 + stg * 16384 + frow * 128;
        int x = frow & 7;
        int u0 = foct * 2;
        CP_ASYNC16(dstRow + ((u0 ^ x) << 4),       src + u0 * 8);
        CP_ASYNC16(dstRow + (((u0 + 1) ^ x) << 4), src + u0 * 8 + 8);
    };
    auto loadA = [&](int ch, float4* v) {
        const float* src = X + (size_t)(mBase + frow) * DIM + ch * BK + foct * 8;
        v[0] = *(const float4*)(src);
        v[1] = *(const float4*)(src + 4);
    };
    auto storeA = [&](const float4* v, int buf) {
        __half h[8], l[8];
        const float* f = (const float*)v;
        #pragma unroll
        for (int i = 0; i < 8; i++) {
            float s = f[i] * SCALE;
            h[i] = __float2half_rn(s);
            l[i] = __float2half_rn(s - __half2float(h[i]));
        }
        uint32_t rowAddr = sb + buf * 16384 + frow * 128;
        int x = frow & 7;
        uint32_t aH = rowAddr + ((foct ^ x) << 4);
        uint32_t aL = rowAddr + (((4 + foct) ^ x) << 4);
        uint4 ph = *(const uint4*)h;
        uint4 pl = *(const uint4*)l;
        asm volatile("st.shared.v4.b32 [%0], {%1,%2,%3,%4};" :: "r"(aH), "r"(ph.x), "r"(ph.y), "r"(ph.z), "r"(ph.w));
        asm volatile("st.shared.v4.b32 [%0], {%1,%2,%3,%4};" :: "r"(aL), "r"(pl.x), "r"(pl.y), "r"(pl.z), "r"(pl.w));
    };

    // prologue: B stages 0,1 in flight; A chunk 0 staged
    {
        issueB(0, 0); CP_COMMIT();
        issueB(1, 1); CP_COMMIT();
        float4 v[2];
        loadA(0, v);
        storeA(v, 0);
    }

    for (int ch = 0; ch < NCHUNK; ch++) {
        const int bstg = ch % 3;
        const int abuf = ch & 1;

        CP_WAIT1();          // B(ch) has landed; B(ch+1) may still fly
        __syncthreads();     // A stores + B stage reuse fence

        // issue B(ch+2) into the stage consumed at ch-1
        if (ch + 2 < NCHUNK) issueB(ch + 2, (ch + 2) % 3);
        CP_COMMIT();

        float4 v[2];
        if (ch + 1 < NCHUNK) loadA(ch + 1, v);

        #pragma unroll
        for (int kst = 0; kst < 2; kst++) {
            const int uH = 2 * kst, uL = 4 + 2 * kst;
            uint32_t aH[2][4], aL[2][4], bH[2][4], bL[2][4];
            LDSM4(aH[0], aAddr(abuf, 0, uH)); LDSM4(aH[1], aAddr(abuf, 1, uH));
            LDSM4(aL[0], aAddr(abuf, 0, uL)); LDSM4(aL[1], aAddr(abuf, 1, uL));
            LDSM4(bH[0], bAddr(bstg, 0, uH)); LDSM4(bH[1], bAddr(bstg, 1, uH));
            LDSM4(bL[0], bAddr(bstg, 0, uL)); LDSM4(bL[1], bAddr(bstg, 1, uL));
            #pragma unroll
            for (int mt = 0; mt < 2; mt++)
                #pragma unroll
                for (int ntp = 0; ntp < 2; ntp++) {
                    mma16(c[mt][ntp * 2],     aH[mt], bH[ntp]);
                    mma16(c[mt][ntp * 2 + 1], aH[mt], bH[ntp] + 2);
                    mma16(c[mt][ntp * 2],     aH[mt], bL[ntp]);
                    mma16(c[mt][ntp * 2 + 1], aH[mt], bL[ntp] + 2);
                    mma16(c[mt][ntp * 2],     aL[mt], bH[ntp]);
                    mma16(c[mt][ntp * 2 + 1], aL[mt], bH[ntp] + 2);
                }
        }

        if (ch + 1 < NCHUNK) storeA(v, abuf ^ 1);
    }

    const int group = lane >> 2, tig = lane & 3;
    #pragma unroll
    for (int mt = 0; mt < 2; mt++) {
        int r0 = mBase + warpM * 32 + mt * 16 + group;
        #pragma unroll
        for (int nt = 0; nt < 4; nt++) {
            int n0 = nBase + warpN * 32 + nt * 8 + tig * 2;
            float be0 = (n0     < N_INNER) ? __ldg(beta + n0)     : 0.0f;
            float be1 = (n0 + 1 < N_INNER) ? __ldg(beta + n0 + 1) : 0.0f;
            float bi0 = (n0     < N_INNER) ? __ldg(bias + n0)     : 0.0f;
            float bi1 = (n0 + 1 < N_INNER) ? __ldg(bias + n0 + 1) : 0.0f;
            float2 o0, o1;
            {
                float z = be0 * (c[mt][nt][0] * SCALE_INV + bi0);
                o0.x = (n0 < N_INNER) ? 1.0f / (1.0f + expf(-z)) : 0.0f;
            }
            {
                float z = be1 * (c[mt][nt][1] * SCALE_INV + bi1);
                o0.y = (n0 + 1 < N_INNER) ? 1.0f / (1.0f + expf(-z)) : 0.0f;
            }
            {
                float z = be0 * (c[mt][nt][2] * SCALE_INV + bi0);
                o1.x = (n0 < N_INNER) ? 1.0f / (1.0f + expf(-z)) : 0.0f;
            }
            {
                float z = be1 * (c[mt][nt][3] * SCALE_INV + bi1);
                o1.y = (n0 + 1 < N_INNER) ? 1.0f / (1.0f + expf(-z)) : 0.0f;
            }
            *(float2*)(g_probs + (size_t)r0 * 256 + n0)       = o0;
            *(float2*)(g_probs + (size_t)(r0 + 8) * 256 + n0) = o1;
        }
    }
}

// ---------------- tree expansion + fused output gather ----------------
__global__ __launch_bounds__(256)
void path_kernel(float* __restrict__ outRows) {
    __shared__ float sp[8][256];
    __shared__ float ls[256];
    __shared__ float red[256];
    const int warp = threadIdx.x >> 5, lane = threadIdx.x & 31;
    const int gw = blockIdx.x * 8 + warp;
    const int nw = gridDim.x * 8;
    const int base = lane * 8;

    ls[threadIdx.x] = 0.0f;
    __syncthreads();

    float lacc[8];
    #pragma unroll
    for (int k = 0; k < 8; k++) lacc[k] = 0.0f;
    float dacc = 0.0f;

    for (int b = gw; b < B_ROWS; b += nw) {
        const float* pr = g_probs + (size_t)b * 256;
        for (int i = lane; i < 256; i += 32) sp[warp][i] = pr[i];
        __syncwarp();

        float pre = 1.0f;
        #pragma unroll
        for (int d = 1; d <= 5; d++) {
            int g = (1 << (d - 1)) - 1 + (base >> (9 - d));
            int bit = (base >> (8 - d)) & 1;
            float pv = sp[warp][g];
            pre *= bit ? pv : (1.0f - pv);
        }
        float leaf[8];
        #pragma unroll
        for (int k = 0; k < 8; k++) {
            int l = base + k;
            float f = pre;
            #pragma unroll
            for (int d = 6; d <= 8; d++) {
                int g = (1 << (d - 1)) - 1 + (l >> (9 - d));
                int bit = (l >> (8 - d)) & 1;
                float pv = sp[warp][g];
                f *= bit ? pv : (1.0f - pv);
            }
            leaf[k] = f;
            lacc[k] += f;
        }

        int t = g_t[b];
        const float* lq = g_logQt + (size_t)t * 256 + base;
        float dl = 0.0f;
        #pragma unroll
        for (int k = 0; k < 8; k++) dl += leaf[k] * lq[k];
        dacc += dl;

        float bv = leaf[0]; int bi = base;
        #pragma unroll
        for (int k = 1; k < 8; k++) if (leaf[k] > bv) { bv = leaf[k]; bi = base + k; }
        for (int off = 16; off; off >>= 1) {
            float ov = __shfl_down_sync(0xffffffffu, bv, off);
            int   oi = __shfl_down_sync(0xffffffffu, bi, off);
            if (ov > bv || (ov == bv && oi < bi)) { bv = ov; bi = oi; }
        }
        bi = __shfl_sync(0xffffffffu, bi, 0);

        const float* q = g_Q + (size_t)bi * OUT_CL;
        float* o = outRows + (size_t)b * OUT_CL;
        #pragma unroll 4
        for (int j = lane; j < OUT_CL; j += 32) o[j] = __ldg(q + j);
        __syncwarp();
    }

    #pragma unroll
    for (int k = 0; k < 8; k++) atomicAdd(&ls[base + k], lacc[k]);
    __syncthreads();
    atomicAdd(&g_leafSum[threadIdx.x], ls[threadIdx.x]);

    red[threadIdx.x] = dacc;
    __syncthreads();
    for (int s = 128; s; s >>= 1) { if (threadIdx.x < s) red[threadIdx.x] += red[threadIdx.x + s]; __syncthreads(); }
    if (threadIdx.x == 0) atomicAdd(&g_lossSum, (double)red[0]);
}

// ---------------- finalize (parallel heap + alpha) ----------------
__global__ void final_kernel(float* __restrict__ out, int writeLoss) {
    __shared__ float H[255];
    __shared__ float Cs[128];
    const int tid = threadIdx.x;

    if (tid < 128) H[127 + tid] = g_leafSum[2 * tid] + g_leafSum[2 * tid + 1];
    __syncthreads();
    for (int n = 64; n >= 1; n >>= 1) {
        int b0 = n - 1;
        if (tid < n) H[b0 + tid] = H[2 * (b0 + tid) + 1] + H[2 * (b0 + tid) + 2];
        __syncthreads();
    }

    float cpart = 0.0f;
    if (tid < 127) {
        int g = tid;
        int d = 32 - __clz(g + 1);
        float lm = 0.1f * exp2f((float)(-d)) * 0.5f;
        float denom = H[g];
        if (denom == 0.0f) denom = 1e-6f;
        float a = H[2 * g + 2] / denom;
        a = fminf(fmaxf(a, 1e-6f), 1.0f - 1e-6f);
        cpart = -lm * (logf(a) + log1pf(-a));
    }
    Cs[tid] = cpart;
    __syncthreads();
    for (int s = 64; s; s >>= 1) { if (tid < s) Cs[tid] += Cs[tid + s]; __syncthreads(); }
    if (tid == 0 && writeLoss) {
        double lt = g_lossSum / (double)B_ROWS;
        out[0] = (float)(-lt + (double)Cs[0]);
    }
}

extern "C" void kernel_launch(void* const* d_in, const int* in_sizes, int n_in,
                              void* d_out, int out_size) {
    const float* x    = (const float*)d_in[0];
    const float* y    = (const float*)d_in[1];
    const float* W    = (const float*)d_in[2];
    const float* bias = (const float*)d_in[3];
    const float* beta = (const float*)d_in[4];
    const float* lp   = (const float*)d_in[5];
    float* out = (float*)d_out;

    int hasLoss = (out_size >= B_ROWS * OUT_CL + 1) ? 1 : 0;
    float* outRows = out + hasLoss;

    static int smemSet = 0;
    if (!smemSet) {
        cudaFuncSetAttribute(gemm_mma_kernel, cudaFuncAttributeMaxDynamicSharedMemorySize, GEMM_SMEM);
        smemSet = 1;
    }

    init_kernel<<<1, 256>>>();
    wsplit_kernel<<<256, 256>>>(W);
    softmax_kernel<<<N_LEAF, 256>>>(lp);
    gemm_mma_kernel<<<dim3(2, 128), 512, GEMM_SMEM>>>(x, bias, beta);
    target_kernel<<<2048, 256>>>(y);
    path_kernel<<<512, 256>>>(outRows);
    final_kernel<<<1, 128>>>(out, hasLoss);
}

// round 16
// speedup vs baseline: 1.7039x; 1.0801x over previous
#include <cuda_runtime.h>
#include <cuda_fp16.h>
#include <cuda_bf16.h>
#include <math.h>
#include <stdint.h>

// Problem constants
#define B_ROWS   16384
#define DIM      2048
#define OUT_CL   1000
#define N_INNER  255
#define N_LEAF   256

#define BK      32
#define NCHUNK  (DIM / BK)
#define SCALE     1024.0f
#define SCALE_INV (1.0f / (1024.0f * 1024.0f))

// ---------------- device scratch ----------------
__device__ float  g_probs[(size_t)B_ROWS * 256];
__device__ float  g_Q[(size_t)N_LEAF * OUT_CL];
__device__ float  g_logQt[(size_t)OUT_CL * N_LEAF];
__device__ float  g_leafSum[N_LEAF];
__device__ double g_lossSum;
__device__ int    g_t[B_ROWS];
// W split to fp16 hi/lo, scaled by 1024: [n][chunk][hi 0..31 | lo 32..63]
__device__ __half g_Wsp[(size_t)256 * DIM * 2];

// ---------------- helpers ----------------
__device__ __forceinline__ uint32_t smem_u32(const void* p) {
    uint32_t a;
    asm("{ .reg .u64 t; cvta.to.shared.u64 t, %1; cvt.u32.u64 %0, t; }" : "=r"(a) : "l"(p));
    return a;
}
__device__ __forceinline__ void mma16(float* c, const uint32_t* a, const uint32_t* b) {
    asm volatile("mma.sync.aligned.m16n8k16.row.col.f32.f16.f16.f32 "
        "{%0,%1,%2,%3}, {%4,%5,%6,%7}, {%8,%9}, {%0,%1,%2,%3};"
        : "+f"(c[0]), "+f"(c[1]), "+f"(c[2]), "+f"(c[3])
        : "r"(a[0]), "r"(a[1]), "r"(a[2]), "r"(a[3]), "r"(b[0]), "r"(b[1]));
}
// f16-accumulate variant (2x tensor rate) for the small cross terms
__device__ __forceinline__ void mma16h(uint32_t* c, const uint32_t* a, const uint32_t* b) {
    asm volatile("mma.sync.aligned.m16n8k16.row.col.f16.f16.f16.f16 "
        "{%0,%1}, {%2,%3,%4,%5}, {%6,%7}, {%0,%1};"
        : "+r"(c[0]), "+r"(c[1])
        : "r"(a[0]), "r"(a[1]), "r"(a[2]), "r"(a[3]), "r"(b[0]), "r"(b[1]));
}
#define LDSM4(r, a) asm volatile("ldmatrix.sync.aligned.m8n8.x4.shared.b16 {%0,%1,%2,%3}, [%4];" \
    : "=r"((r)[0]), "=r"((r)[1]), "=r"((r)[2]), "=r"((r)[3]) : "r"(a))
#define CP_ASYNC16(dst, src) asm volatile("cp.async.cg.shared.global [%0], [%1], 16;" :: "r"(dst), "l"(src))
#define CP_COMMIT()          asm volatile("cp.async.commit_group;")
#define CP_WAIT1()           asm volatile("cp.async.wait_group 1;" ::: "memory")

// ---------------- W split to fp16 hi/lo (scaled by 1024) + init ----------------
__global__ void wsplit_kernel(const float* __restrict__ W) {
    int n = blockIdx.x;
    if (blockIdx.x == 0) {
        if (threadIdx.x < N_LEAF) g_leafSum[threadIdx.x] = 0.0f;
        if (threadIdx.x == 0) g_lossSum = 0.0;
    }
    for (int k = threadIdx.x; k < DIM; k += 256) {
        float w = (n < N_INNER) ? W[(size_t)n * DIM + k] * SCALE : 0.0f;
        __half h = __float2half_rn(w);
        __half l = __float2half_rn(w - __half2float(h));
        int ch = k >> 5, s = k & 31;
        size_t base = (size_t)n * (DIM * 2) + ch * 64;
        g_Wsp[base + s]      = h;
        g_Wsp[base + 32 + s] = l;
    }
}

// ---------------- log_softmax of leaf_params ----------------
__global__ void softmax_kernel(const float* __restrict__ lp) {
    __shared__ float red[256];
    int r = blockIdx.x;
    int tid = threadIdx.x;
    const float* row = lp + (size_t)r * OUT_CL;

    float m = -INFINITY;
    for (int j = tid; j < OUT_CL; j += 256) m = fmaxf(m, row[j]);
    red[tid] = m; __syncthreads();
    for (int s = 128; s; s >>= 1) { if (tid < s) red[tid] = fmaxf(red[tid], red[tid + s]); __syncthreads(); }
    float rowmax = red[0];
    __syncthreads();

    float sum = 0.0f;
    for (int j = tid; j < OUT_CL; j += 256) sum += expf(row[j] - rowmax);
    red[tid] = sum; __syncthreads();
    for (int s = 128; s; s >>= 1) { if (tid < s) red[tid] += red[tid + s]; __syncthreads(); }
    float lse = rowmax + logf(red[0]);

    for (int j = tid; j < OUT_CL; j += 256) {
        float lq = row[j] - lse;
        g_Q[(size_t)r * OUT_CL + j] = expf(lq);
        g_logQt[(size_t)j * N_LEAF + r] = lq;
    }
}

// ---------------- target extraction (one-hot, float4 scan, early exit) ----------------
__global__ void target_kernel(const float* __restrict__ y) {
    int warp = threadIdx.x >> 5, lane = threadIdx.x & 31;
    int gw = blockIdx.x * (blockDim.x >> 5) + warp;
    int nw = gridDim.x * (blockDim.x >> 5);
    for (int b = gw; b < B_ROWS; b += nw) {
        const float* row = y + (size_t)b * OUT_CL;
        int found = 0;
        for (int jb = 0; jb < OUT_CL; jb += 128) {
            int j4 = jb + lane * 4;
            float4 v = make_float4(0.f, 0.f, 0.f, 0.f);
            if (j4 + 3 < OUT_CL) v = *(const float4*)(row + j4);
            int loc = (v.x > 0.5f) ? j4 : (v.y > 0.5f) ? j4 + 1 :
                      (v.z > 0.5f) ? j4 + 2 : (v.w > 0.5f) ? j4 + 3 : -1;
            unsigned msk = __ballot_sync(0xffffffffu, loc >= 0);
            if (msk) {
                int src = __ffs(msk) - 1;
                found = __shfl_sync(0xffffffffu, loc, src);
                break;
            }
        }
        if (lane == 0) g_t[b] = found;
    }
}

// ---------------- fp16 3-product mma GEMM (cross terms f16-acc) ----------------
// CTA: 512 threads = 16 warps (4 M x 4 N), tile 128x128, warp tile 32x32.
// A: 2 buffers x 16KB @0 (in-kernel split). B: 3 stages x 16KB @32768.
#define GEMM_SMEM (2 * 16384 + 3 * 16384)

__global__ __launch_bounds__(512, 1)
void gemm_mma_kernel(const float* __restrict__ X,
                     const float* __restrict__ bias, const float* __restrict__ beta) {
    extern __shared__ __align__(16) char smemc[];
    const int tid  = threadIdx.x;
    const int lane = tid & 31, wid = tid >> 5;
    const int warpM = wid & 3, warpN = wid >> 2;
    const int mBase = blockIdx.y * 128;
    const int nBase = blockIdx.x * 128;
    const uint32_t sb = smem_u32(smemc);

    const int aRow = warpM * 32 + (lane & 15);
    const int aU   = lane >> 4;
    const int bRow = warpN * 32 + (lane & 7) + ((lane >> 4) << 3);
    const int bU   = (lane >> 3) & 1;

    const int frow = tid >> 2;
    const int foct = tid & 3;

    float c[2][4][4];          // hi*hi accumulators (fp32)
    uint32_t h16[2][4][2];     // cross-term accumulators (f16x2, double-rate MMA)
    #pragma unroll
    for (int i = 0; i < 2; i++)
        #pragma unroll
        for (int j = 0; j < 4; j++) {
            #pragma unroll
            for (int k = 0; k < 4; k++) c[i][j][k] = 0.0f;
            h16[i][j][0] = 0u; h16[i][j][1] = 0u;
        }

    auto aAddr = [&](int buf, int mt, int u0) -> uint32_t {
        int row = aRow + mt * 16;
        return sb + buf * 16384 + row * 128 + (((u0 + aU) ^ (row & 7)) << 4);
    };
    auto bAddr = [&](int stg, int ntp, int u0) -> uint32_t {
        int row = bRow + ntp * 16;
        return sb + 32768 + stg * 16384 + row * 128 + (((u0 + bU) ^ (row & 7)) << 4);
    };

    auto issueB = [&](int ch, int stg) {
        const __half* src = g_Wsp + (size_t)(nBase + frow) * (DIM * 2) + ch * 64;
        uint32_t dstRow = sb + 32768 + stg * 16384 + frow * 128;
        int x = frow & 7;
        int u0 = foct * 2;
        CP_ASYNC16(dstRow + ((u0 ^ x) << 4),       src + u0 * 8);
        CP_ASYNC16(dstRow + (((u0 + 1) ^ x) << 4), src + u0 * 8 + 8);
    };
    auto loadA = [&](int ch, float4* v) {
        const float* src = X + (size_t)(mBase + frow) * DIM + ch * BK + foct * 8;
        v[0] = *(const float4*)(src);
        v[1] = *(const float4*)(src + 4);
    };
    auto storeA = [&](const float4* v, int buf) {
        __half h[8], l[8];
        const float* f = (const float*)v;
        #pragma unroll
        for (int i = 0; i < 8; i++) {
            float s = f[i] * SCALE;
            h[i] = __float2half_rn(s);
            l[i] = __float2half_rn(s - __half2float(h[i]));
        }
        uint32_t rowAddr = sb + buf * 16384 + frow * 128;
        int x = frow & 7;
        uint32_t aH = rowAddr + ((foct ^ x) << 4);
        uint32_t aL = rowAddr + (((4 + foct) ^ x) << 4);
        uint4 ph = *(const uint4*)h;
        uint4 pl = *(const uint4*)l;
        asm volatile("st.shared.v4.b32 [%0], {%1,%2,%3,%4};" :: "r"(aH), "r"(ph.x), "r"(ph.y), "r"(ph.z), "r"(ph.w));
        asm volatile("st.shared.v4.b32 [%0], {%1,%2,%3,%4};" :: "r"(aL), "r"(pl.x), "r"(pl.y), "r"(pl.z), "r"(pl.w));
    };

    // prologue
    {
        issueB(0, 0); CP_COMMIT();
        issueB(1, 1); CP_COMMIT();
        float4 v[2];
        loadA(0, v);
        storeA(v, 0);
    }

    for (int ch = 0; ch < NCHUNK; ch++) {
        const int bstg = ch % 3;
        const int abuf = ch & 1;

        CP_WAIT1();
        __syncthreads();

        if (ch + 2 < NCHUNK) issueB(ch + 2, (ch + 2) % 3);
        CP_COMMIT();

        float4 v[2];
        if (ch + 1 < NCHUNK) loadA(ch + 1, v);

        #pragma unroll
        for (int kst = 0; kst < 2; kst++) {
            const int uH = 2 * kst, uL = 4 + 2 * kst;
            uint32_t aH[2][4], aL[2][4], bH[2][4], bL[2][4];
            LDSM4(aH[0], aAddr(abuf, 0, uH)); LDSM4(aH[1], aAddr(abuf, 1, uH));
            LDSM4(aL[0], aAddr(abuf, 0, uL)); LDSM4(aL[1], aAddr(abuf, 1, uL));
            LDSM4(bH[0], bAddr(bstg, 0, uH)); LDSM4(bH[1], bAddr(bstg, 1, uH));
            LDSM4(bL[0], bAddr(bstg, 0, uL)); LDSM4(bL[1], bAddr(bstg, 1, uL));
            #pragma unroll
            for (int mt = 0; mt < 2; mt++)
                #pragma unroll
                for (int ntp = 0; ntp < 2; ntp++) {
                    mma16(c[mt][ntp * 2],     aH[mt], bH[ntp]);       // hi*hi fp32
                    mma16(c[mt][ntp * 2 + 1], aH[mt], bH[ntp] + 2);
                    mma16h(h16[mt][ntp * 2],     aH[mt], bL[ntp]);    // hi*lo f16 acc
                    mma16h(h16[mt][ntp * 2 + 1], aH[mt], bL[ntp] + 2);
                    mma16h(h16[mt][ntp * 2],     aL[mt], bH[ntp]);    // lo*hi f16 acc
                    mma16h(h16[mt][ntp * 2 + 1], aL[mt], bH[ntp] + 2);
                }
        }

        if (ch + 1 < NCHUNK) storeA(v, abuf ^ 1);
    }

    const int group = lane >> 2, tig = lane & 3;
    #pragma unroll
    for (int mt = 0; mt < 2; mt++) {
        int r0 = mBase + warpM * 32 + mt * 16 + group;
        #pragma unroll
        for (int nt = 0; nt < 4; nt++) {
            int n0 = nBase + warpN * 32 + nt * 8 + tig * 2;
            float be0 = (n0     < N_INNER) ? __ldg(beta + n0)     : 0.0f;
            float be1 = (n0 + 1 < N_INNER) ? __ldg(beta + n0 + 1) : 0.0f;
            float bi0 = (n0     < N_INNER) ? __ldg(bias + n0)     : 0.0f;
            float bi1 = (n0 + 1 < N_INNER) ? __ldg(bias + n0 + 1) : 0.0f;
            float2 x01 = __half22float2(*reinterpret_cast<__half2*>(&h16[mt][nt][0]));
            float2 x23 = __half22float2(*reinterpret_cast<__half2*>(&h16[mt][nt][1]));
            float2 o0, o1;
            {
                float z = be0 * ((c[mt][nt][0] + x01.x) * SCALE_INV + bi0);
                o0.x = (n0 < N_INNER) ? 1.0f / (1.0f + expf(-z)) : 0.0f;
            }
            {
                float z = be1 * ((c[mt][nt][1] + x01.y) * SCALE_INV + bi1);
                o0.y = (n0 + 1 < N_INNER) ? 1.0f / (1.0f + expf(-z)) : 0.0f;
            }
            {
                float z = be0 * ((c[mt][nt][2] + x23.x) * SCALE_INV + bi0);
                o1.x = (n0 < N_INNER) ? 1.0f / (1.0f + expf(-z)) : 0.0f;
            }
            {
                float z = be1 * ((c[mt][nt][3] + x23.y) * SCALE_INV + bi1);
                o1.y = (n0 + 1 < N_INNER) ? 1.0f / (1.0f + expf(-z)) : 0.0f;
            }
            *(float2*)(g_probs + (size_t)r0 * 256 + n0)       = o0;
            *(float2*)(g_probs + (size_t)(r0 + 8) * 256 + n0) = o1;
        }
    }
}

// ---------------- tree expansion + fused output gather ----------------
__global__ __launch_bounds__(256)
void path_kernel(float* __restrict__ outRows) {
    __shared__ float sp[8][256];
    __shared__ float ls[256];
    __shared__ float red[256];
    const int warp = threadIdx.x >> 5, lane = threadIdx.x & 31;
    const int gw = blockIdx.x * 8 + warp;
    const int nw = gridDim.x * 8;
    const int base = lane * 8;

    ls[threadIdx.x] = 0.0f;
    __syncthreads();

    float lacc[8];
    #pragma unroll
    for (int k = 0; k < 8; k++) lacc[k] = 0.0f;
    float dacc = 0.0f;

    for (int b = gw; b < B_ROWS; b += nw) {
        const float* pr = g_probs + (size_t)b * 256;
        for (int i = lane; i < 256; i += 32) sp[warp][i] = pr[i];
        __syncwarp();

        float pre = 1.0f;
        #pragma unroll
        for (int d = 1; d <= 5; d++) {
            int g = (1 << (d - 1)) - 1 + (base >> (9 - d));
            int bit = (base >> (8 - d)) & 1;
            float pv = sp[warp][g];
            pre *= bit ? pv : (1.0f - pv);
        }
        float leaf[8];
        #pragma unroll
        for (int k = 0; k < 8; k++) {
            int l = base + k;
            float f = pre;
            #pragma unroll
            for (int d = 6; d <= 8; d++) {
                int g = (1 << (d - 1)) - 1 + (l >> (9 - d));
                int bit = (l >> (8 - d)) & 1;
                float pv = sp[warp][g];
                f *= bit ? pv : (1.0f - pv);
            }
            leaf[k] = f;
            lacc[k] += f;
        }

        int t = g_t[b];
        const float* lq = g_logQt + (size_t)t * 256 + base;
        float dl = 0.0f;
        #pragma unroll
        for (int k = 0; k < 8; k++) dl += leaf[k] * lq[k];
        dacc += dl;

        float bv = leaf[0]; int bi = base;
        #pragma unroll
        for (int k = 1; k < 8; k++) if (leaf[k] > bv) { bv = leaf[k]; bi = base + k; }
        for (int off = 16; off; off >>= 1) {
            float ov = __shfl_down_sync(0xffffffffu, bv, off);
            int   oi = __shfl_down_sync(0xffffffffu, bi, off);
            if (ov > bv || (ov == bv && oi < bi)) { bv = ov; bi = oi; }
        }
        bi = __shfl_sync(0xffffffffu, bi, 0);

        const float* q = g_Q + (size_t)bi * OUT_CL;
        float* o = outRows + (size_t)b * OUT_CL;
        #pragma unroll 4
        for (int j = lane; j < OUT_CL; j += 32) o[j] = __ldg(q + j);
        __syncwarp();
    }

    #pragma unroll
    for (int k = 0; k < 8; k++) atomicAdd(&ls[base + k], lacc[k]);
    __syncthreads();
    atomicAdd(&g_leafSum[threadIdx.x], ls[threadIdx.x]);

    red[threadIdx.x] = dacc;
    __syncthreads();
    for (int s = 128; s; s >>= 1) { if (threadIdx.x < s) red[threadIdx.x] += red[threadIdx.x + s]; __syncthreads(); }
    if (threadIdx.x == 0) atomicAdd(&g_lossSum, (double)red[0]);
}

// ---------------- finalize (parallel heap + alpha) ----------------
__global__ void final_kernel(float* __restrict__ out, int writeLoss) {
    __shared__ float H[255];
    __shared__ float Cs[128];
    const int tid = threadIdx.x;

    if (tid < 128) H[127 + tid] = g_leafSum[2 * tid] + g_leafSum[2 * tid + 1];
    __syncthreads();
    for (int n = 64; n >= 1; n >>= 1) {
        int b0 = n - 1;
        if (tid < n) H[b0 + tid] = H[2 * (b0 + tid) + 1] + H[2 * (b0 + tid) + 2];
        __syncthreads();
    }

    float cpart = 0.0f;
    if (tid < 127) {
        int g = tid;
        int d = 32 - __clz(g + 1);
        float lm = 0.1f * exp2f((float)(-d)) * 0.5f;
        float denom = H[g];
        if (denom == 0.0f) denom = 1e-6f;
        float a = H[2 * g + 2] / denom;
        a = fminf(fmaxf(a, 1e-6f), 1.0f - 1e-6f);
        cpart = -lm * (logf(a) + log1pf(-a));
    }
    Cs[tid] = cpart;
    __syncthreads();
    for (int s = 64; s; s >>= 1) { if (tid < s) Cs[tid] += Cs[tid + s]; __syncthreads(); }
    if (tid == 0 && writeLoss) {
        double lt = g_lossSum / (double)B_ROWS;
        out[0] = (float)(-lt + (double)Cs[0]);
    }
}

extern "C" void kernel_launch(void* const* d_in, const int* in_sizes, int n_in,
                              void* d_out, int out_size) {
    const float* x    = (const float*)d_in[0];
    const float* y    = (const float*)d_in[1];
    const float* W    = (const float*)d_in[2];
    const float* bias = (const float*)d_in[3];
    const float* beta = (const float*)d_in[4];
    const float* lp   = (const float*)d_in[5];
    float* out = (float*)d_out;

    int hasLoss = (out_size >= B_ROWS * OUT_CL + 1) ? 1 : 0;
    float* outRows = out + hasLoss;

    static int smemSet = 0;
    if (!smemSet) {
        cudaFuncSetAttribute(gemm_mma_kernel, cudaFuncAttributeMaxDynamicSharedMemorySize, GEMM_SMEM);
        smemSet = 1;
    }

    wsplit_kernel<<<256, 256>>>(W);
    softmax_kernel<<<N_LEAF, 256>>>(lp);
    gemm_mma_kernel<<<dim3(2, 128), 512, GEMM_SMEM>>>(x, bias, beta);
    target_kernel<<<2048, 256>>>(y);
    path_kernel<<<512, 256>>>(outRows);
    final_kernel<<<1, 128>>>(out, hasLoss);
}